// round 16
// baseline (speedup 1.0000x reference)
#include <cuda_runtime.h>
#include <cuda_fp16.h>
#include <math.h>
#include <stdint.h>

// Problem constants
#define NN 8192
#define DD 256
#define GG 2048
#define BM 128
#define BN 128
#define BK 64                 // K elems per chunk (fp16: 128 B per row)
#define NC (DD / BK)          // 4 K-chunks
#define NTILE (NN / BN)       // 64 column tiles
#define NPAIR (NTILE * (NTILE + 1) / 2)   // 2080 upper-tri tiles
#define NPOS 64               // converter + positives blocks
#define NTOT (NPOS + NPAIR)   // 2144 total blocks
#define NSLIM 128             // slim slices (must be < min concurrent CTAs ~296)
#define GPB (GG / NSLIM)      // 16 groups per slim slice
#define TPAR 0.04f
#define SCALE 36.067376022224085f   // log2(e)/T

__device__ __half g_xh[NN * DD];          // x rounded to fp16 (RN), 4MB
__device__ float  g_partial[NN * NTILE];  // [row][coltile] masked exp rowsum partials
__device__ float  g_mu[GG];               // margin / T per group
__device__ float  g_slice_sum[NSLIM];
__device__ int    g_cvt_done;             // all zero-init; reset by final block
__device__ int    g_cvt_flag;
__device__ int    g_tile_done;
__device__ int    g_slim_done;

// ------------------------------------------------------------------ helpers
__device__ __forceinline__ float ex2f_(float v) {
    float r; asm("ex2.approx.f32 %0, %1;" : "=f"(r) : "f"(v)); return r;
}
__device__ __forceinline__ uint32_t smem_u32(const void* p) {
    uint32_t a;
    asm("{ .reg .u64 t; cvta.to.shared.u64 t, %1; cvt.u32.u64 %0, t; }" : "=r"(a) : "l"(p));
    return a;
}
__device__ __forceinline__ void ldsm_x4(uint32_t r[4], uint32_t addr) {
    asm volatile("ldmatrix.sync.aligned.m8n8.x4.shared.b16 {%0,%1,%2,%3}, [%4];"
                 : "=r"(r[0]), "=r"(r[1]), "=r"(r[2]), "=r"(r[3]) : "r"(addr));
}
__device__ __forceinline__ void mma_f16acc(uint32_t c[2], const uint32_t a[4],
                                           const uint32_t b0, const uint32_t b1) {
    asm volatile(
        "mma.sync.aligned.m16n8k16.row.col.f16.f16.f16.f16 "
        "{%0,%1}, {%2,%3,%4,%5}, {%6,%7}, {%0,%1};"
        : "+r"(c[0]), "+r"(c[1])
        : "r"(a[0]), "r"(a[1]), "r"(a[2]), "r"(a[3]), "r"(b0), "r"(b1));
}
__device__ __forceinline__ int ld_acquire(const int* p) {
    int v; asm volatile("ld.acquire.gpu.b32 %0, [%1];" : "=r"(v) : "l"(p) : "memory");
    return v;
}
__device__ __forceinline__ void st_release(int* p, int v) {
    asm volatile("st.release.gpu.b32 [%0], %1;" :: "l"(p), "r"(v) : "memory");
}
__device__ __forceinline__ void nsleep(unsigned t) {
    asm volatile("nanosleep.u32 %0;" :: "r"(t));
}

// SMEM: 2 stages x (A 16KB + B 16KB) = 64KB + epilogue scratch
#define STAGE_BYTES 32768
#define SM_ROWPART 65536
#define SM_COLPART (65536 + 1024)
#define SMEM_BYTES (65536 + 2048)

// ---------------------------------------------------------------------------
// Single fused kernel.
//   bid < NPOS : convert x->fp16 (cooperative), release gate, then positives.
//   else       : wait gate, fp16 m16n8k16 Gram tile (R15 floor config).
//   Tail (all blocks): completion counter; last NSLIM blocks run the group
//   reduction + softplus; very last performs fixed-order mean, writes out,
//   resets counters for graph replay.
// ---------------------------------------------------------------------------
__global__ void __launch_bounds__(128, 3) fused(const float* __restrict__ x,
                                                float* __restrict__ out) {
    const int tid = threadIdx.x;
    const int lane = tid & 31, wid = tid >> 5;
    __shared__ int sprev;
    __shared__ float wsum[GPB];

    if (blockIdx.x < NPOS) {
        // ---- phase 1: convert slice of x to fp16 (8 floats per unit) ----
        // 262144 units / 8192 threads = 32 units per thread, fully coalesced
        {
            const int base = blockIdx.x * 128 + tid;
            #pragma unroll 4
            for (int it = 0; it < 32; it++) {
                const int i = (base + it * 8192) * 8;
                float4 a = *reinterpret_cast<const float4*>(x + i);
                float4 b = *reinterpret_cast<const float4*>(x + i + 4);
                __half2 h0 = __floats2half2_rn(a.x, a.y);
                __half2 h1 = __floats2half2_rn(a.z, a.w);
                __half2 h2 = __floats2half2_rn(b.x, b.y);
                __half2 h3 = __floats2half2_rn(b.z, b.w);
                uint4 o;
                o.x = *reinterpret_cast<uint32_t*>(&h0);
                o.y = *reinterpret_cast<uint32_t*>(&h1);
                o.z = *reinterpret_cast<uint32_t*>(&h2);
                o.w = *reinterpret_cast<uint32_t*>(&h3);
                *reinterpret_cast<uint4*>(g_xh + i) = o;
            }
        }
        __threadfence();
        __syncthreads();
        if (tid == 0) {
            int prev = atomicAdd(&g_cvt_done, 1);
            if (prev == NPOS - 1) st_release(&g_cvt_flag, 1);
        }

        // ---- phase 2: positives (margins) — reads only fp32 x ----
        {
            const int pair = lane & 15;
            const int half = lane >> 4;
            const int pi = pair >> 2, pj = pair & 3;
            #pragma unroll 1
            for (int q = 0; q < 8; q++) {
                const int g = blockIdx.x * 32 + wid * 8 + q;
                const float* xi = x + (size_t)(4 * g + pi) * DD + half * 128;
                const float* xj = x + (size_t)(4 * g + pj) * DD + half * 128;
                float dot = 0.f;
                #pragma unroll
                for (int k = 0; k < 128; k += 4) {
                    float4 a = *reinterpret_cast<const float4*>(xi + k);
                    float4 b = *reinterpret_cast<const float4*>(xj + k);
                    dot += a.x * b.x + a.y * b.y + a.z * b.z + a.w * b.w;
                }
                dot += __shfl_down_sync(0xffffffffu, dot, 16);
                float en = ex2f_(-dot * SCALE);
                float rowsum = en;
                rowsum += __shfl_xor_sync(0xffffffffu, rowsum, 1);
                rowsum += __shfl_xor_sync(0xffffffffu, rowsum, 2);
                float inv = 0.25f / rowsum;
                float sum_en = en, sum_inv = inv;
                #pragma unroll
                for (int m = 1; m < 16; m <<= 1) {
                    sum_en  += __shfl_xor_sync(0xffffffffu, sum_en,  m, 16);
                    sum_inv += __shfl_xor_sync(0xffffffffu, sum_inv, m, 16);
                }
                if (lane == 0) {
                    float hard_pos  = -TPAR * logf(sum_en);
                    float least_pos =  TPAR * logf(sum_inv);
                    float alpha = (hard_pos >= 0.f)
                        ? (2.f * least_pos * hard_pos / (hard_pos + least_pos)) : 0.f;
                    float margin = alpha * hard_pos + (1.f - alpha) * least_pos;
                    g_mu[g] = margin / TPAR;
                }
            }
        }
    } else {
        // ---- Gram tile: wait for conversion gate ----
        if (tid == 0) {
            while (ld_acquire(&g_cvt_flag) == 0) nsleep(128);
        }
        __syncthreads();

        extern __shared__ char smem[];
        const uint32_t sb = smem_u32(smem);
        const int warp_m = wid & 1;
        const int warp_n = wid >> 1;

        const int bid = blockIdx.x - NPOS;
        int bi = (int)((129.0f - sqrtf(16641.0f - 8.0f * (float)bid)) * 0.5f);
        if (bi > 63) bi = 63;
        while (bi > 0 && (NTILE * bi - (bi * (bi - 1)) / 2) > bid) bi--;
        while ((NTILE * (bi + 1) - ((bi + 1) * bi) / 2) <= bid) bi++;
        const int bj = bi + (bid - (NTILE * bi - (bi * (bi - 1)) / 2));
        const int R0 = bi * BM, C0 = bj * BN;
        const bool diag = (bi == bj);

        uint32_t cc[4][8][2];
        #pragma unroll
        for (int m = 0; m < 4; m++)
            #pragma unroll
            for (int n = 0; n < 8; n++) { cc[m][n][0] = 0u; cc[m][n][1] = 0u; }

        const int prow = tid >> 3;
        const int pq   = tid & 7;
        const __half* srcA0 = g_xh + (size_t)(R0 + prow) * DD + pq * 8;
        const __half* srcB0 = g_xh + (size_t)(C0 + prow) * DD + pq * 8;
        const uint32_t dst0 = (uint32_t)(prow * 128 + ((pq ^ (prow & 7)) << 4));

        const int aSel = lane >> 4;
        const int aXor = lane & 7;
        const uint32_t aRel = (uint32_t)((warp_m * 64 + (lane & 15)) * 128);
        const int bSel = (lane >> 3) & 1;
        const int bXor = lane & 7;
        const uint32_t bRel = 16384u +
            (uint32_t)((warp_n * 64 + ((lane >> 4) << 3) + (lane & 7)) * 128);

        // Prologue: chunk 0 -> stage 0
        {
            float4 ra[8], rb[8];
            #pragma unroll
            for (int i = 0; i < 8; i++)
                ra[i] = *reinterpret_cast<const float4*>(srcA0 + (size_t)i * 16 * DD);
            #pragma unroll
            for (int i = 0; i < 8; i++)
                rb[i] = *reinterpret_cast<const float4*>(srcB0 + (size_t)i * 16 * DD);
            #pragma unroll
            for (int i = 0; i < 8; i++) {
                *reinterpret_cast<float4*>(smem + dst0 + i * 2048u)          = ra[i];
                *reinterpret_cast<float4*>(smem + 16384u + dst0 + i * 2048u) = rb[i];
            }
        }

        #pragma unroll
        for (int c = 0; c < NC; c++) {
            const int s = c & 1;
            __syncthreads();
            const uint32_t sa  = sb + (uint32_t)(s * STAGE_BYTES) + aRel;
            const uint32_t sbb = sb + (uint32_t)(s * STAGE_BYTES) + bRel;
            char* wp = smem + (s ^ 1) * STAGE_BYTES;
            const bool np = (c + 1 < NC);
            const int koff = (c + 1) * BK;

            uint32_t af[4][4], bq[16];
            auto ldfrag = [&](int ks) {
                const uint32_t axo = (uint32_t)(((2 * ks + aSel) ^ aXor) << 4);
                const uint32_t bxo = (uint32_t)(((2 * ks + bSel) ^ bXor) << 4);
                #pragma unroll
                for (int p = 0; p < 4; p++) ldsm_x4(&bq[4 * p], sbb + p * 2048u + bxo);
                #pragma unroll
                for (int m = 0; m < 4; m++) ldsm_x4(af[m], sa + m * 2048u + axo);
            };
            auto domma = [&]() {
                #pragma unroll
                for (int m = 0; m < 4; m++)
                    #pragma unroll
                    for (int n = 0; n < 8; n++)
                        mma_f16acc(cc[m][n], af[m], bq[2 * n], bq[2 * n + 1]);
            };

            float4 ra[8];
            if (np) {
                #pragma unroll
                for (int i = 0; i < 8; i++)
                    ra[i] = *reinterpret_cast<const float4*>(srcA0 + koff + (size_t)i * 16 * DD);
            }
            ldfrag(0); domma();
            ldfrag(1); domma();
            float4 rb[8];
            if (np) {
                #pragma unroll
                for (int i = 0; i < 8; i++)
                    *reinterpret_cast<float4*>(wp + dst0 + i * 2048u) = ra[i];
                #pragma unroll
                for (int i = 0; i < 8; i++)
                    rb[i] = *reinterpret_cast<const float4*>(srcB0 + koff + (size_t)i * 16 * DD);
            }
            ldfrag(2); domma();
            ldfrag(3); domma();
            if (np) {
                #pragma unroll
                for (int i = 0; i < 8; i++)
                    *reinterpret_cast<float4*>(wp + 16384u + dst0 + i * 2048u) = rb[i];
            }
        }

        // Epilogue
        float* rowpart = reinterpret_cast<float*>(smem + SM_ROWPART);
        float* colpart = reinterpret_cast<float*>(smem + SM_COLPART);
        __syncthreads();

        if (diag) {
            #pragma unroll
            for (int mt = 0; mt < 4; mt++) {
                const int rl = warp_m * 64 + mt * 16 + (lane >> 2);
                const int r_lo = R0 + rl, r_hi = r_lo + 8;
                float lo = 0.f, hi = 0.f;
                #pragma unroll
                for (int nt = 0; nt < 8; nt++) {
                    const int c0 = C0 + warp_n * 64 + nt * 8 + 2 * (lane & 3);
                    float2 v0 = __half22float2(*reinterpret_cast<__half2*>(&cc[mt][nt][0]));
                    float2 v1 = __half22float2(*reinterpret_cast<__half2*>(&cc[mt][nt][1]));
                    float e;
                    e = ex2f_(v0.x * SCALE); if ((r_lo >> 2) == (c0 >> 2))       e = 0.f; lo += e;
                    e = ex2f_(v0.y * SCALE); if ((r_lo >> 2) == ((c0 + 1) >> 2)) e = 0.f; lo += e;
                    e = ex2f_(v1.x * SCALE); if ((r_hi >> 2) == (c0 >> 2))       e = 0.f; hi += e;
                    e = ex2f_(v1.y * SCALE); if ((r_hi >> 2) == ((c0 + 1) >> 2)) e = 0.f; hi += e;
                }
                lo += __shfl_xor_sync(0xffffffffu, lo, 1); lo += __shfl_xor_sync(0xffffffffu, lo, 2);
                hi += __shfl_xor_sync(0xffffffffu, hi, 1); hi += __shfl_xor_sync(0xffffffffu, hi, 2);
                if ((lane & 3) == 0) {
                    rowpart[rl * 2 + warp_n]       = lo;
                    rowpart[(rl + 8) * 2 + warp_n] = hi;
                }
            }
        } else {
            float colacc[8][2];
            #pragma unroll
            for (int nt = 0; nt < 8; nt++) { colacc[nt][0] = 0.f; colacc[nt][1] = 0.f; }
            #pragma unroll
            for (int mt = 0; mt < 4; mt++) {
                const int rl = warp_m * 64 + mt * 16 + (lane >> 2);
                float lo = 0.f, hi = 0.f;
                #pragma unroll
                for (int nt = 0; nt < 8; nt++) {
                    float2 v0 = __half22float2(*reinterpret_cast<__half2*>(&cc[mt][nt][0]));
                    float2 v1 = __half22float2(*reinterpret_cast<__half2*>(&cc[mt][nt][1]));
                    float e0 = ex2f_(v0.x * SCALE);
                    float e1 = ex2f_(v0.y * SCALE);
                    float e2 = ex2f_(v1.x * SCALE);
                    float e3 = ex2f_(v1.y * SCALE);
                    lo += e0 + e1;  hi += e2 + e3;
                    colacc[nt][0] += e0 + e2;
                    colacc[nt][1] += e1 + e3;
                }
                lo += __shfl_xor_sync(0xffffffffu, lo, 1); lo += __shfl_xor_sync(0xffffffffu, lo, 2);
                hi += __shfl_xor_sync(0xffffffffu, hi, 1); hi += __shfl_xor_sync(0xffffffffu, hi, 2);
                if ((lane & 3) == 0) {
                    rowpart[rl * 2 + warp_n]       = lo;
                    rowpart[(rl + 8) * 2 + warp_n] = hi;
                }
            }
            #pragma unroll
            for (int nt = 0; nt < 8; nt++) {
                #pragma unroll
                for (int p = 0; p < 2; p++) {
                    float v = colacc[nt][p];
                    v += __shfl_xor_sync(0xffffffffu, v, 4);
                    v += __shfl_xor_sync(0xffffffffu, v, 8);
                    v += __shfl_xor_sync(0xffffffffu, v, 16);
                    colacc[nt][p] = v;
                }
            }
            if (lane < 4) {
                #pragma unroll
                for (int nt = 0; nt < 8; nt++) {
                    const int cl = warp_n * 64 + nt * 8 + 2 * lane;
                    colpart[cl * 2 + warp_m]       = colacc[nt][0];
                    colpart[(cl + 1) * 2 + warp_m] = colacc[nt][1];
                }
            }
        }
        __syncthreads();
        {
            const float s2 = rowpart[tid * 2 + 0] + rowpart[tid * 2 + 1];
            g_partial[(size_t)(R0 + tid) * NTILE + bj] = s2;
            if (!diag) {
                const float c2 = colpart[tid * 2 + 0] + colpart[tid * 2 + 1];
                g_partial[(size_t)(C0 + tid) * NTILE + bi] = c2;
            }
        }
    }

    // -------------------- common tail: completion + distributed slim ---------
    __threadfence();
    __syncthreads();
    if (tid == 0) sprev = atomicAdd(&g_tile_done, 1);
    __syncthreads();
    const int prev = sprev;
    if (prev < NTOT - NSLIM) return;

    // This block owns slim slice = prev - (NTOT - NSLIM). Wait for all blocks.
    const int slice = prev - (NTOT - NSLIM);
    if (tid == 0) {
        while (ld_acquire(&g_tile_done) < NTOT) nsleep(128);
    }
    __syncthreads();

    // 16 groups per slice; each warp handles 4 groups sequentially.
    #pragma unroll 1
    for (int q = 0; q < 4; q++) {
        const int g = slice * GPB + wid * 4 + q;
        const float4* part = reinterpret_cast<const float4*>(g_partial + (size_t)(4 * g) * NTILE);
        float4 p0 = part[lane];
        float4 p1 = part[lane + 32];
        float S = (p0.x + p0.y) + (p0.z + p0.w) + (p1.x + p1.y) + (p1.z + p1.w);
        #pragma unroll
        for (int m = 1; m < 32; m <<= 1) S += __shfl_xor_sync(0xffffffffu, S, m);
        if (lane == 0) {
            float z = logf(S) - g_mu[g];
            wsum[wid * 4 + q] = (z > 0.f) ? (z + log1pf(expf(-z))) : log1pf(expf(z));
        }
    }
    __syncthreads();
    if (tid == 0) {
        float bs = 0.f;
        #pragma unroll
        for (int w = 0; w < GPB; w++) bs += wsum[w];       // fixed order
        g_slice_sum[slice] = bs;
        __threadfence();
        sprev = atomicAdd(&g_slim_done, 1);
    }
    __syncthreads();
    if (sprev == NSLIM - 1) {
        __threadfence();
        if (tid < 32) {
            float s = 0.f;
            #pragma unroll
            for (int t = tid; t < NSLIM; t += 32) s += g_slice_sum[t];   // fixed order
            #pragma unroll
            for (int m = 1; m < 32; m <<= 1) s += __shfl_xor_sync(0xffffffffu, s, m);
            if (tid == 0) {
                out[0] = s * (1.f / (float)GG);
                // reset for next graph replay
                g_cvt_done = 0; g_cvt_flag = 0; g_tile_done = 0; g_slim_done = 0;
            }
        }
    }
}

// ---------------------------------------------------------------------------
extern "C" void kernel_launch(void* const* d_in, const int* in_sizes, int n_in,
                              void* d_out, int out_size) {
    const float* x = (const float*)d_in[0];
    static int configured = 0;
    if (!configured) {
        cudaFuncSetAttribute(fused, cudaFuncAttributeMaxDynamicSharedMemorySize, SMEM_BYTES);
        configured = 1;
    }
    fused<<<NTOT, 128, SMEM_BYTES>>>(x, (float*)d_out);
}

// round 17
// speedup vs baseline: 1.0477x; 1.0477x over previous
#include <cuda_runtime.h>
#include <cuda_fp16.h>
#include <math.h>
#include <stdint.h>

// Problem constants
#define NN 8192
#define DD 256
#define GG 2048
#define BM 128
#define BN 128
#define BK 64                 // K elems per chunk (fp16: 128 B per row)
#define NC (DD / BK)          // 4 K-chunks
#define NTILE (NN / BN)       // 64 column tiles
#define NPAIR (NTILE * (NTILE + 1) / 2)   // 2080 upper-tri tiles
#define NPOS 64               // positives blocks (32 groups each)
#define NTOT (NPOS + NPAIR)   // 2144 blocks
#define NSLIM 128             // slim slices (< min concurrent CTAs ~296)
#define GPB (GG / NSLIM)      // 16 groups per slim slice
#define TPAR 0.04f
#define SCALE 36.067376022224085f   // log2(e)/T

__device__ __half g_xh[NN * DD];          // x rounded to fp16 (RN), 4MB
__device__ float  g_partial[NN * NTILE];  // [row][coltile] masked exp rowsum partials
__device__ float  g_mu[GG];               // margin / T per group
__device__ float  g_slice_sum[NSLIM];
__device__ int    g_tile_done;            // zero-init; reset by final block
__device__ int    g_slim_done;

// ------------------------------------------------------------------ helpers
__device__ __forceinline__ float ex2f_(float v) {
    float r; asm("ex2.approx.f32 %0, %1;" : "=f"(r) : "f"(v)); return r;
}
__device__ __forceinline__ uint32_t smem_u32(const void* p) {
    uint32_t a;
    asm("{ .reg .u64 t; cvta.to.shared.u64 t, %1; cvt.u32.u64 %0, t; }" : "=r"(a) : "l"(p));
    return a;
}
__device__ __forceinline__ void ldsm_x4(uint32_t r[4], uint32_t addr) {
    asm volatile("ldmatrix.sync.aligned.m8n8.x4.shared.b16 {%0,%1,%2,%3}, [%4];"
                 : "=r"(r[0]), "=r"(r[1]), "=r"(r[2]), "=r"(r[3]) : "r"(addr));
}
__device__ __forceinline__ void mma_f16acc(uint32_t c[2], const uint32_t a[4],
                                           const uint32_t b0, const uint32_t b1) {
    asm volatile(
        "mma.sync.aligned.m16n8k16.row.col.f16.f16.f16.f16 "
        "{%0,%1}, {%2,%3,%4,%5}, {%6,%7}, {%0,%1};"
        : "+r"(c[0]), "+r"(c[1])
        : "r"(a[0]), "r"(a[1]), "r"(a[2]), "r"(a[3]), "r"(b0), "r"(b1));
}
__device__ __forceinline__ int ld_acquire(const int* p) {
    int v; asm volatile("ld.acquire.gpu.b32 %0, [%1];" : "=r"(v) : "l"(p) : "memory");
    return v;
}
__device__ __forceinline__ void nsleep(unsigned t) {
    asm volatile("nanosleep.u32 %0;" :: "r"(t));
}

// SMEM: 2 stages x (A 16KB + B 16KB) = 64KB + epilogue scratch
#define STAGE_BYTES 32768
#define SM_ROWPART 65536
#define SM_COLPART (65536 + 1024)
#define SMEM_BYTES (65536 + 2048)

// ---------------------------------------------------------------------------
// Kernel 0: round x to fp16 (RN) once
// ---------------------------------------------------------------------------
__global__ void __launch_bounds__(256) cvt_kernel(const float* __restrict__ x) {
    const int i = (blockIdx.x * 256 + threadIdx.x) * 8;
    float4 a = *reinterpret_cast<const float4*>(x + i);
    float4 b = *reinterpret_cast<const float4*>(x + i + 4);
    __half2 h0 = __floats2half2_rn(a.x, a.y);
    __half2 h1 = __floats2half2_rn(a.z, a.w);
    __half2 h2 = __floats2half2_rn(b.x, b.y);
    __half2 h3 = __floats2half2_rn(b.z, b.w);
    uint4 o;
    o.x = *reinterpret_cast<uint32_t*>(&h0);
    o.y = *reinterpret_cast<uint32_t*>(&h1);
    o.z = *reinterpret_cast<uint32_t*>(&h2);
    o.w = *reinterpret_cast<uint32_t*>(&h3);
    *reinterpret_cast<uint4*>(g_xh + i) = o;
}

// ---------------------------------------------------------------------------
// Kernel 1: bid<NPOS: positives margins. else: fp16 Gram tile (R15 floor).
// Common tail: last NSLIM finishers run the group reduction + fused mean.
// ---------------------------------------------------------------------------
__global__ void __launch_bounds__(128, 3) gram_mma(const float* __restrict__ x,
                                                   float* __restrict__ out) {
    const int tid = threadIdx.x;
    const int lane = tid & 31, wid = tid >> 5;
    __shared__ int sprev;
    __shared__ float wsum[GPB];

    if (blockIdx.x < NPOS) {
        // ---- positives: 32 groups per block (8 per warp), exact fp32 path ----
        const int pair = lane & 15;
        const int half = lane >> 4;
        const int pi = pair >> 2, pj = pair & 3;
        #pragma unroll 1
        for (int q = 0; q < 8; q++) {
            const int g = blockIdx.x * 32 + wid * 8 + q;
            const float* xi = x + (size_t)(4 * g + pi) * DD + half * 128;
            const float* xj = x + (size_t)(4 * g + pj) * DD + half * 128;
            float dot = 0.f;
            #pragma unroll
            for (int k = 0; k < 128; k += 4) {
                float4 a = *reinterpret_cast<const float4*>(xi + k);
                float4 b = *reinterpret_cast<const float4*>(xj + k);
                dot += a.x * b.x + a.y * b.y + a.z * b.z + a.w * b.w;
            }
            dot += __shfl_down_sync(0xffffffffu, dot, 16);
            float en = ex2f_(-dot * SCALE);
            float rowsum = en;
            rowsum += __shfl_xor_sync(0xffffffffu, rowsum, 1);
            rowsum += __shfl_xor_sync(0xffffffffu, rowsum, 2);
            float inv = 0.25f / rowsum;
            float sum_en = en, sum_inv = inv;
            #pragma unroll
            for (int m = 1; m < 16; m <<= 1) {
                sum_en  += __shfl_xor_sync(0xffffffffu, sum_en,  m, 16);
                sum_inv += __shfl_xor_sync(0xffffffffu, sum_inv, m, 16);
            }
            if (lane == 0) {
                float hard_pos  = -TPAR * logf(sum_en);
                float least_pos =  TPAR * logf(sum_inv);
                float alpha = (hard_pos >= 0.f)
                    ? (2.f * least_pos * hard_pos / (hard_pos + least_pos)) : 0.f;
                float margin = alpha * hard_pos + (1.f - alpha) * least_pos;
                g_mu[g] = margin / TPAR;
            }
        }
    } else {
        // ---- Gram tile (R15 floor config) ----
        extern __shared__ char smem[];
        const uint32_t sb = smem_u32(smem);
        const int warp_m = wid & 1;
        const int warp_n = wid >> 1;

        const int bid = blockIdx.x - NPOS;
        int bi = (int)((129.0f - sqrtf(16641.0f - 8.0f * (float)bid)) * 0.5f);
        if (bi > 63) bi = 63;
        while (bi > 0 && (NTILE * bi - (bi * (bi - 1)) / 2) > bid) bi--;
        while ((NTILE * (bi + 1) - ((bi + 1) * bi) / 2) <= bid) bi++;
        const int bj = bi + (bid - (NTILE * bi - (bi * (bi - 1)) / 2));
        const int R0 = bi * BM, C0 = bj * BN;
        const bool diag = (bi == bj);

        uint32_t cc[4][8][2];
        #pragma unroll
        for (int m = 0; m < 4; m++)
            #pragma unroll
            for (int n = 0; n < 8; n++) { cc[m][n][0] = 0u; cc[m][n][1] = 0u; }

        const int prow = tid >> 3;
        const int pq   = tid & 7;
        const __half* srcA0 = g_xh + (size_t)(R0 + prow) * DD + pq * 8;
        const __half* srcB0 = g_xh + (size_t)(C0 + prow) * DD + pq * 8;
        const uint32_t dst0 = (uint32_t)(prow * 128 + ((pq ^ (prow & 7)) << 4));

        const int aSel = lane >> 4;
        const int aXor = lane & 7;
        const uint32_t aRel = (uint32_t)((warp_m * 64 + (lane & 15)) * 128);
        const int bSel = (lane >> 3) & 1;
        const int bXor = lane & 7;
        const uint32_t bRel = 16384u +
            (uint32_t)((warp_n * 64 + ((lane >> 4) << 3) + (lane & 7)) * 128);

        // Prologue: chunk 0 -> stage 0
        {
            float4 ra[8], rb[8];
            #pragma unroll
            for (int i = 0; i < 8; i++)
                ra[i] = *reinterpret_cast<const float4*>(srcA0 + (size_t)i * 16 * DD);
            #pragma unroll
            for (int i = 0; i < 8; i++)
                rb[i] = *reinterpret_cast<const float4*>(srcB0 + (size_t)i * 16 * DD);
            #pragma unroll
            for (int i = 0; i < 8; i++) {
                *reinterpret_cast<float4*>(smem + dst0 + i * 2048u)          = ra[i];
                *reinterpret_cast<float4*>(smem + 16384u + dst0 + i * 2048u) = rb[i];
            }
        }

        #pragma unroll
        for (int c = 0; c < NC; c++) {
            const int s = c & 1;
            __syncthreads();
            const uint32_t sa  = sb + (uint32_t)(s * STAGE_BYTES) + aRel;
            const uint32_t sbb = sb + (uint32_t)(s * STAGE_BYTES) + bRel;
            char* wp = smem + (s ^ 1) * STAGE_BYTES;
            const bool np = (c + 1 < NC);
            const int koff = (c + 1) * BK;

            uint32_t af[4][4], bq[16];
            auto ldfrag = [&](int ks) {
                const uint32_t axo = (uint32_t)(((2 * ks + aSel) ^ aXor) << 4);
                const uint32_t bxo = (uint32_t)(((2 * ks + bSel) ^ bXor) << 4);
                #pragma unroll
                for (int p = 0; p < 4; p++) ldsm_x4(&bq[4 * p], sbb + p * 2048u + bxo);
                #pragma unroll
                for (int m = 0; m < 4; m++) ldsm_x4(af[m], sa + m * 2048u + axo);
            };
            auto domma = [&]() {
                #pragma unroll
                for (int m = 0; m < 4; m++)
                    #pragma unroll
                    for (int n = 0; n < 8; n++)
                        mma_f16acc(cc[m][n], af[m], bq[2 * n], bq[2 * n + 1]);
            };

            float4 ra[8];
            if (np) {
                #pragma unroll
                for (int i = 0; i < 8; i++)
                    ra[i] = *reinterpret_cast<const float4*>(srcA0 + koff + (size_t)i * 16 * DD);
            }
            ldfrag(0); domma();
            ldfrag(1); domma();
            float4 rb[8];
            if (np) {
                #pragma unroll
                for (int i = 0; i < 8; i++)
                    *reinterpret_cast<float4*>(wp + dst0 + i * 2048u) = ra[i];
                #pragma unroll
                for (int i = 0; i < 8; i++)
                    rb[i] = *reinterpret_cast<const float4*>(srcB0 + koff + (size_t)i * 16 * DD);
            }
            ldfrag(2); domma();
            ldfrag(3); domma();
            if (np) {
                #pragma unroll
                for (int i = 0; i < 8; i++)
                    *reinterpret_cast<float4*>(wp + 16384u + dst0 + i * 2048u) = rb[i];
            }
        }

        // Epilogue: unpack half2 -> fp32 exp/mask/row+col sums
        float* rowpart = reinterpret_cast<float*>(smem + SM_ROWPART);
        float* colpart = reinterpret_cast<float*>(smem + SM_COLPART);
        __syncthreads();

        if (diag) {
            #pragma unroll
            for (int mt = 0; mt < 4; mt++) {
                const int rl = warp_m * 64 + mt * 16 + (lane >> 2);
                const int r_lo = R0 + rl, r_hi = r_lo + 8;
                float lo = 0.f, hi = 0.f;
                #pragma unroll
                for (int nt = 0; nt < 8; nt++) {
                    const int c0 = C0 + warp_n * 64 + nt * 8 + 2 * (lane & 3);
                    float2 v0 = __half22float2(*reinterpret_cast<__half2*>(&cc[mt][nt][0]));
                    float2 v1 = __half22float2(*reinterpret_cast<__half2*>(&cc[mt][nt][1]));
                    float e;
                    e = ex2f_(v0.x * SCALE); if ((r_lo >> 2) == (c0 >> 2))       e = 0.f; lo += e;
                    e = ex2f_(v0.y * SCALE); if ((r_lo >> 2) == ((c0 + 1) >> 2)) e = 0.f; lo += e;
                    e = ex2f_(v1.x * SCALE); if ((r_hi >> 2) == (c0 >> 2))       e = 0.f; hi += e;
                    e = ex2f_(v1.y * SCALE); if ((r_hi >> 2) == ((c0 + 1) >> 2)) e = 0.f; hi += e;
                }
                lo += __shfl_xor_sync(0xffffffffu, lo, 1); lo += __shfl_xor_sync(0xffffffffu, lo, 2);
                hi += __shfl_xor_sync(0xffffffffu, hi, 1); hi += __shfl_xor_sync(0xffffffffu, hi, 2);
                if ((lane & 3) == 0) {
                    rowpart[rl * 2 + warp_n]       = lo;
                    rowpart[(rl + 8) * 2 + warp_n] = hi;
                }
            }
        } else {
            float colacc[8][2];
            #pragma unroll
            for (int nt = 0; nt < 8; nt++) { colacc[nt][0] = 0.f; colacc[nt][1] = 0.f; }
            #pragma unroll
            for (int mt = 0; mt < 4; mt++) {
                const int rl = warp_m * 64 + mt * 16 + (lane >> 2);
                float lo = 0.f, hi = 0.f;
                #pragma unroll
                for (int nt = 0; nt < 8; nt++) {
                    float2 v0 = __half22float2(*reinterpret_cast<__half2*>(&cc[mt][nt][0]));
                    float2 v1 = __half22float2(*reinterpret_cast<__half2*>(&cc[mt][nt][1]));
                    float e0 = ex2f_(v0.x * SCALE);
                    float e1 = ex2f_(v0.y * SCALE);
                    float e2 = ex2f_(v1.x * SCALE);
                    float e3 = ex2f_(v1.y * SCALE);
                    lo += e0 + e1;  hi += e2 + e3;
                    colacc[nt][0] += e0 + e2;
                    colacc[nt][1] += e1 + e3;
                }
                lo += __shfl_xor_sync(0xffffffffu, lo, 1); lo += __shfl_xor_sync(0xffffffffu, lo, 2);
                hi += __shfl_xor_sync(0xffffffffu, hi, 1); hi += __shfl_xor_sync(0xffffffffu, hi, 2);
                if ((lane & 3) == 0) {
                    rowpart[rl * 2 + warp_n]       = lo;
                    rowpart[(rl + 8) * 2 + warp_n] = hi;
                }
            }
            #pragma unroll
            for (int nt = 0; nt < 8; nt++) {
                #pragma unroll
                for (int p = 0; p < 2; p++) {
                    float v = colacc[nt][p];
                    v += __shfl_xor_sync(0xffffffffu, v, 4);
                    v += __shfl_xor_sync(0xffffffffu, v, 8);
                    v += __shfl_xor_sync(0xffffffffu, v, 16);
                    colacc[nt][p] = v;
                }
            }
            if (lane < 4) {
                #pragma unroll
                for (int nt = 0; nt < 8; nt++) {
                    const int cl = warp_n * 64 + nt * 8 + 2 * lane;
                    colpart[cl * 2 + warp_m]       = colacc[nt][0];
                    colpart[(cl + 1) * 2 + warp_m] = colacc[nt][1];
                }
            }
        }
        __syncthreads();
        {
            const float s2 = rowpart[tid * 2 + 0] + rowpart[tid * 2 + 1];
            g_partial[(size_t)(R0 + tid) * NTILE + bj] = s2;
            if (!diag) {
                const float c2 = colpart[tid * 2 + 0] + colpart[tid * 2 + 1];
                g_partial[(size_t)(C0 + tid) * NTILE + bi] = c2;
            }
        }
    }

    // ---- common tail: completion counter + distributed slim reduction ----
    __threadfence();
    __syncthreads();
    if (tid == 0) sprev = atomicAdd(&g_tile_done, 1);
    __syncthreads();
    const int prev = sprev;
    if (prev < NTOT - NSLIM) return;

    const int slice = prev - (NTOT - NSLIM);
    if (tid == 0) {
        while (ld_acquire(&g_tile_done) < NTOT) nsleep(64);
    }
    __syncthreads();

    // 16 groups per slice; each warp handles 4 groups.
    #pragma unroll 1
    for (int q = 0; q < 4; q++) {
        const int g = slice * GPB + wid * 4 + q;
        const float4* part = reinterpret_cast<const float4*>(g_partial + (size_t)(4 * g) * NTILE);
        float4 p0 = part[lane];
        float4 p1 = part[lane + 32];
        float S = (p0.x + p0.y) + (p0.z + p0.w) + (p1.x + p1.y) + (p1.z + p1.w);
        #pragma unroll
        for (int m = 1; m < 32; m <<= 1) S += __shfl_xor_sync(0xffffffffu, S, m);
        if (lane == 0) {
            float z = logf(S) - g_mu[g];
            wsum[wid * 4 + q] = (z > 0.f) ? (z + log1pf(expf(-z))) : log1pf(expf(z));
        }
    }
    __syncthreads();
    if (tid == 0) {
        float bs = 0.f;
        #pragma unroll
        for (int w = 0; w < GPB; w++) bs += wsum[w];       // fixed order
        g_slice_sum[slice] = bs;
        __threadfence();
        sprev = atomicAdd(&g_slim_done, 1);
    }
    __syncthreads();
    if (sprev == NSLIM - 1) {
        __threadfence();
        if (tid < 32) {
            float s = 0.f;
            #pragma unroll
            for (int t = tid; t < NSLIM; t += 32) s += g_slice_sum[t];   // fixed order
            #pragma unroll
            for (int m = 1; m < 32; m <<= 1) s += __shfl_xor_sync(0xffffffffu, s, m);
            if (tid == 0) {
                out[0] = s * (1.f / (float)GG);
                g_tile_done = 0;      // reset for graph replay
                g_slim_done = 0;
            }
        }
    }
}

// ---------------------------------------------------------------------------
extern "C" void kernel_launch(void* const* d_in, const int* in_sizes, int n_in,
                              void* d_out, int out_size) {
    const float* x = (const float*)d_in[0];
    static int configured = 0;
    if (!configured) {
        cudaFuncSetAttribute(gram_mma, cudaFuncAttributeMaxDynamicSharedMemorySize, SMEM_BYTES);
        configured = 1;
    }
    cvt_kernel<<<NN * DD / 2048, 256>>>(x);
    gram_mma<<<NTOT, 128, SMEM_BYTES>>>(x, (float*)d_out);
}